// round 11
// baseline (speedup 1.0000x reference)
#include <cuda_runtime.h>
#include <cuda_bf16.h>
#include <cstdint>
#include <math.h>

#define BB 4
#define SS 1024
#define DD 1024
#define HH 16
#define DKK 64

// ---------------------------------------------------------------------------
// Portable PTX helpers (sm_80+: mma.sync bf16, ldmatrix, cp.async)
// ---------------------------------------------------------------------------
__device__ __forceinline__ uint32_t smem_u32(const void* p) {
    uint32_t a;
    asm("{ .reg .u64 t; cvta.to.shared.u64 t, %1; cvt.u32.u64 %0, t; }" : "=r"(a) : "l"(p));
    return a;
}
#define CPASYNC16(dst, src) \
    asm volatile("cp.async.cg.shared.global [%0], [%1], 16;" :: "r"(dst), "l"(src) : "memory")
#define CPCOMMIT() asm volatile("cp.async.commit_group;" ::: "memory")
#define CPWAITG(n) asm volatile("cp.async.wait_group %0;" :: "n"(n) : "memory")

#define LDSM4(r0, r1, r2, r3, addr) \
    asm volatile("ldmatrix.sync.aligned.m8n8.x4.shared.b16 {%0,%1,%2,%3}, [%4];" \
                 : "=r"(r0), "=r"(r1), "=r"(r2), "=r"(r3) : "r"(addr))

#define MMA16816(c, a, b) \
    asm volatile("mma.sync.aligned.m16n8k16.row.col.f32.bf16.bf16.f32 " \
                 "{%0,%1,%2,%3},{%4,%5,%6,%7},{%8,%9},{%0,%1,%2,%3};" \
                 : "+f"((c)[0]), "+f"((c)[1]), "+f"((c)[2]), "+f"((c)[3]) \
                 : "r"((a)[0]), "r"((a)[1]), "r"((a)[2]), "r"((a)[3]), \
                   "r"((b)[0]), "r"((b)[1]))

// ---------------------------------------------------------------------------
// Scratch (static device globals)
// ---------------------------------------------------------------------------
__device__ __nv_bfloat16 g_Xhi[BB * SS * DD];
__device__ __nv_bfloat16 g_Xlo[BB * SS * DD];
__device__ __nv_bfloat16 g_WGhi[DD * DD];
__device__ __nv_bfloat16 g_WGlo[DD * DD];
__device__ __nv_bfloat16 g_WkThi[DD * DD];
__device__ __nv_bfloat16 g_WkTlo[DD * DD];
__device__ __nv_bfloat16 g_WGKThi[DD * DD];
__device__ __nv_bfloat16 g_WGKTlo[DD * DD];
__device__ float  g_biask[DD];
__device__ float  g_g0[BB * DD];
__device__ float  g_q0[BB * DD];
__device__ float  g_scores[BB * HH * SS];
__device__ float  g_row0[BB * HH * SS];
__device__ float2 g_tab[SS * 32];          // (cos, sin) for pos t, freq p

// ---------------------------------------------------------------------------
// RoPE sincos table: tab[t*32+p] = (cos(t*inv_p), sin(t*inv_p))
// ---------------------------------------------------------------------------
__global__ void tab_kernel(float2* __restrict__ tab)
{
    int idx = blockIdx.x * 256 + threadIdx.x;   // 32768 total
    int t = idx >> 5, p = idx & 31;
    float inv = exp2f(-(float)p * 0.41524101186092029f);  // 10000^(-p/32)
    float sn, cs;
    sincosf((float)t * inv, &sn, &cs);
    tab[idx] = make_float2(cs, sn);
}

// ---------------------------------------------------------------------------
// fp32 -> bf16 hi/lo split
// ---------------------------------------------------------------------------
__global__ void split_kernel(const float4* __restrict__ in,
                             __nv_bfloat162* __restrict__ hi,
                             __nv_bfloat162* __restrict__ lo, int n4)
{
    int i = blockIdx.x * 256 + threadIdx.x;
    if (i >= n4) return;
    float4 v = in[i];
    __nv_bfloat16 hx = __float2bfloat16(v.x), hy = __float2bfloat16(v.y);
    __nv_bfloat16 hz = __float2bfloat16(v.z), hw = __float2bfloat16(v.w);
    __nv_bfloat162 a, b;
    a.x = hx; a.y = hy; b.x = hz; b.y = hw;
    hi[2 * i] = a; hi[2 * i + 1] = b;
    __nv_bfloat162 c, d;
    c.x = __float2bfloat16(v.x - __bfloat162float(hx));
    c.y = __float2bfloat16(v.y - __bfloat162float(hy));
    d.x = __float2bfloat16(v.z - __bfloat162float(hz));
    d.y = __float2bfloat16(v.w - __bfloat162float(hw));
    lo[2 * i] = c; lo[2 * i + 1] = d;
}

// Transpose + split: out[c][r] = in[r][c], 1024x1024
__global__ void transpose_split_kernel(const float* __restrict__ in,
                                       __nv_bfloat16* __restrict__ thi,
                                       __nv_bfloat16* __restrict__ tlo)
{
    __shared__ float t[32][33];
    int c0 = blockIdx.x * 32, r0 = blockIdx.y * 32;
    int tx = threadIdx.x, ty = threadIdx.y;
#pragma unroll
    for (int k = 0; k < 4; k++)
        t[ty + 8 * k][tx] = in[(size_t)(r0 + ty + 8 * k) * 1024 + c0 + tx];
    __syncthreads();
#pragma unroll
    for (int k = 0; k < 4; k++) {
        float v = t[tx][ty + 8 * k];
        __nv_bfloat16 h = __float2bfloat16(v);
        size_t o = (size_t)(c0 + ty + 8 * k) * 1024 + r0 + tx;
        thi[o] = h;
        tlo[o] = __float2bfloat16(v - __bfloat162float(h));
    }
}

// ---------------------------------------------------------------------------
// Fast GEMV v3: out[b*1024 + j] = bias[j] + sum_i x[b][i] * W[i*1024 + j]
// grid (16, nb), 256 thr = 8 k-groups x 32 lanes; float2/lane (64 cols/blk),
// fully unrolled k-loop (16 float2 loads in flight per thread).
// ---------------------------------------------------------------------------
__global__ __launch_bounds__(256) void gemv_fast(const float* __restrict__ x,
                                                 const float* __restrict__ W,
                                                 const float* __restrict__ bv,
                                                 float* __restrict__ out,
                                                 long long xstride)
{
    __shared__ float xs[1024];
    __shared__ float2 red[8][32];
    const int b = blockIdx.y;
    const int tid = threadIdx.x;
    const int lane = tid & 31, ig = tid >> 5;
    const float* xr = x + (long long)b * xstride;
    for (int i = tid; i < 1024; i += 256) xs[i] = xr[i];
    __syncthreads();

    const int j = blockIdx.x * 64 + lane * 2;
    const float* Wp = W + (long long)(ig * 128) * 1024 + j;
    float a0 = 0.f, a1 = 0.f;
#pragma unroll 16
    for (int i = 0; i < 128; i++) {
        float2 w = *(const float2*)(Wp + (long long)i * 1024);
        float xv = xs[ig * 128 + i];
        a0 = fmaf(xv, w.x, a0);
        a1 = fmaf(xv, w.y, a1);
    }
    red[ig][lane] = make_float2(a0, a1);
    __syncthreads();
    if (tid < 64) {
        int jo = blockIdx.x * 64 + tid;
        float s = bv[jo];
#pragma unroll
        for (int g = 0; g < 8; g++)
            s += (tid & 1) ? red[g][tid >> 1].y : red[g][tid >> 1].x;
        out[b * 1024 + jo] = s;
    }
}

// ---------------------------------------------------------------------------
// mma.sync bf16 GEMM: C[m,n] = sum_k A[m,k]*B[n,k], 3-term hi/lo split.
// CTA MTILE x 128, 8 warps (2m x 4n). K chunks of 32, FOUR cp.async stages,
// ONE __syncthreads per chunk (fill stage (ch+2)&3 is never concurrently
// read: readers are at iter ch-1 (stage (ch-1)&3) or behind this iter's
// collective barrier). smem row = 128B: [hi k0..31 | lo k0..31], SW128.
// mode 0: split-write bf16 Chi/Clo
// mode 1 (MTILE=128 only): scores[b,h,t] = q0[b,h,:] . rope_t(v + bias) / 8
// ---------------------------------------------------------------------------
template <int MTILE>
__global__ __launch_bounds__(256) void mmagemm(
    const __nv_bfloat16* __restrict__ Ahi, const __nv_bfloat16* __restrict__ Alo,
    const __nv_bfloat16* __restrict__ Bhi, const __nv_bfloat16* __restrict__ Blo,
    int mode,
    const float* __restrict__ bias, const float* __restrict__ q0,
    const float2* __restrict__ tab, float* __restrict__ scores,
    __nv_bfloat16* __restrict__ Chi, __nv_bfloat16* __restrict__ Clo)
{
    constexpr int MT = MTILE / 32;               // m-subtiles per warp
    constexpr int AIT = MTILE / 32;              // A cp.async tasks per thread
    constexpr uint32_t STAGE = (MTILE + 128) * 128;
    constexpr uint32_t BOFF = MTILE * 128;

    extern __shared__ char dyn[];
    uint32_t dynb = smem_u32(dyn);
    const uint32_t sbase = (dynb + 1023) & ~1023u;   // 1KB-aligned smem base

    const int tid = threadIdx.x;
    const int wid = tid >> 5, lane = tid & 31;
    const int gid = lane >> 2, tig = lane & 3;
    const int m0 = blockIdx.y * MTILE, n0 = blockIdx.x * 128;
    const int wm = (wid >> 2) * (MTILE / 2);    // warp m offset
    const int wn = (wid & 3) * 32;              // warp n offset (0..96)

    // ---- cp.async task precompute ------------------------------------------
    const __nv_bfloat16* aSrc[AIT];
    const __nv_bfloat16* bSrc[4];
    uint32_t aDst[AIT], bDst[4];
#pragma unroll
    for (int it = 0; it < AIT; it++) {
        int ix = it * 256 + tid;
        int r = ix >> 3, seg = ix & 7;      // r: row ; seg: 16B segment
        const __nv_bfloat16* ah = (seg < 4) ? Ahi : Alo;
        aSrc[it] = ah + (size_t)(m0 + r) * 1024 + (seg & 3) * 8;
        aDst[it] = sbase + r * 128 + ((seg * 16) ^ ((r & 7) << 4));
    }
#pragma unroll
    for (int it = 0; it < 4; it++) {
        int ix = it * 256 + tid;
        int r = ix >> 3, seg = ix & 7;
        const __nv_bfloat16* bh = (seg < 4) ? Bhi : Blo;
        bSrc[it] = bh + (size_t)(n0 + r) * 1024 + (seg & 3) * 8;
        bDst[it] = sbase + BOFF + r * 128 + ((seg * 16) ^ ((r & 7) << 4));
    }

    // ---- ldmatrix address precompute ---------------------------------------
    const uint32_t xorv = (lane & 7) << 4;          // swizzle XOR (const/thread)
    const uint32_t ksel = (lane >> 4) * 16;         // k-half selector
    uint32_t aRow[MT], bRow[2];
#pragma unroll
    for (int mt = 0; mt < MT; mt++) aRow[mt] = (wm + mt * 16 + (lane & 15)) * 128;
#pragma unroll
    for (int ng = 0; ng < 2; ng++)  bRow[ng] = BOFF + (wn + ng * 16 + (lane & 15)) * 128;

    float acc[MT][4][4];
#pragma unroll
    for (int mt = 0; mt < MT; mt++)
#pragma unroll
        for (int nt = 0; nt < 4; nt++)
#pragma unroll
            for (int i = 0; i < 4; i++) acc[mt][nt][i] = 0.f;

    // ---- prologue: chunks 0,1 into stages 0,1 ------------------------------
#pragma unroll
    for (int pre = 0; pre < 2; pre++) {
        const uint32_t so = pre * STAGE;
        const int ko = pre * 32;
#pragma unroll
        for (int it = 0; it < AIT; it++) CPASYNC16(aDst[it] + so, aSrc[it] + ko);
#pragma unroll
        for (int it = 0; it < 4; it++)   CPASYNC16(bDst[it] + so, bSrc[it] + ko);
        CPCOMMIT();
    }

#pragma unroll 1
    for (int ch = 0; ch < 32; ch++) {
        if (ch < 30) {
            const uint32_t so = (uint32_t)((ch + 2) & 3) * STAGE;
            const int ko = (ch + 2) * 32;
#pragma unroll
            for (int it = 0; it < AIT; it++) CPASYNC16(aDst[it] + so, aSrc[it] + ko);
#pragma unroll
            for (int it = 0; it < 4; it++)   CPASYNC16(bDst[it] + so, bSrc[it] + ko);
            CPCOMMIT();
            CPWAITG(2);
        } else if (ch == 30) {
            CPWAITG(1);
        } else {
            CPWAITG(0);
        }
        __syncthreads();           // single barrier per chunk (4-stage ring)

        const uint32_t As = sbase + (uint32_t)(ch & 3) * STAGE;
#pragma unroll
        for (int ks = 0; ks < 2; ks++) {
            const uint32_t khi = (ks * 32 + ksel) ^ xorv;
            const uint32_t klo = (64 + ks * 32 + ksel) ^ xorv;
            uint32_t ah[MT][4], al[MT][4], bh[4][2], bl[4][2];
#pragma unroll
            for (int mt = 0; mt < MT; mt++) {
                LDSM4(ah[mt][0], ah[mt][1], ah[mt][2], ah[mt][3], As + aRow[mt] + khi);
                LDSM4(al[mt][0], al[mt][1], al[mt][2], al[mt][3], As + aRow[mt] + klo);
            }
#pragma unroll
            for (int ng = 0; ng < 2; ng++) {
                uint32_t r0, r1, r2, r3;
                LDSM4(r0, r1, r2, r3, As + bRow[ng] + khi);
                bh[2 * ng][0] = r0; bh[2 * ng][1] = r2;
                bh[2 * ng + 1][0] = r1; bh[2 * ng + 1][1] = r3;
                LDSM4(r0, r1, r2, r3, As + bRow[ng] + klo);
                bl[2 * ng][0] = r0; bl[2 * ng][1] = r2;
                bl[2 * ng + 1][0] = r1; bl[2 * ng + 1][1] = r3;
            }
#pragma unroll
            for (int mt = 0; mt < MT; mt++)
#pragma unroll
                for (int nt = 0; nt < 4; nt++) {
                    MMA16816(acc[mt][nt], ah[mt], bh[nt]);
                    MMA16816(acc[mt][nt], ah[mt], bl[nt]);
                    MMA16816(acc[mt][nt], al[mt], bh[nt]);
                }
        }
    }

    // ---- epilogue ----------------------------------------------------------
    if (mode == 1) {
        // Fused: rope(v+bias), dot with q0, reduce -> scores[b, h, t]
        const int b = m0 >> 10;
        const int tbase = m0 & 1023;
        float2 bb[4], qv[4];
        const float2* tabp[4];
#pragma unroll
        for (int nt = 0; nt < 4; nt++) {
            int col = n0 + wn + nt * 8 + 2 * tig;
            bb[nt] = *(const float2*)(bias + col);
            qv[nt] = *(const float2*)(q0 + b * 1024 + col);
            tabp[nt] = tab + ((col & 63) >> 1);
        }
        float* spart = (float*)dyn;      // [MTILE][4] partials
#pragma unroll
        for (int mt = 0; mt < MT; mt++) {
#pragma unroll
            for (int half = 0; half < 2; half++) {
                int rl = wm + mt * 16 + gid + half * 8;      // local row
                int t = tbase + rl;
                float p_acc = 0.f;
#pragma unroll
                for (int nt = 0; nt < 4; nt++) {
                    float2 cssn = tabp[nt][t * 32];
                    float v0 = acc[mt][nt][half * 2]     + bb[nt].x;
                    float v1 = acc[mt][nt][half * 2 + 1] + bb[nt].y;
                    float kw0 = v0 * cssn.x - v1 * cssn.y;
                    float kw1 = v1 * cssn.x + v0 * cssn.y;
                    p_acc = fmaf(qv[nt].x, kw0, p_acc);
                    p_acc = fmaf(qv[nt].y, kw1, p_acc);
                }
                p_acc += __shfl_xor_sync(0xffffffffu, p_acc, 1);
                p_acc += __shfl_xor_sync(0xffffffffu, p_acc, 2);
                if (tig == 0) spart[rl * 4 + (wn >> 5)] = p_acc;
            }
        }
        __syncthreads();
        if (tid < MTILE) {
            int t = tbase + tid;
            float s0 = (spart[tid * 4 + 0] + spart[tid * 4 + 1]) * 0.125f;
            float s1 = (spart[tid * 4 + 2] + spart[tid * 4 + 3]) * 0.125f;
            int h0 = n0 >> 6;
            scores[((b * 16 + h0)     << 10) + t] = s0;
            scores[((b * 16 + h0 + 1) << 10) + t] = s1;
        }
    } else {
#pragma unroll
        for (int mt = 0; mt < MT; mt++) {
#pragma unroll
            for (int half = 0; half < 2; half++) {
                int row = m0 + wm + mt * 16 + gid + half * 8;
#pragma unroll
                for (int nt = 0; nt < 4; nt++) {
                    int col = n0 + wn + nt * 8 + 2 * tig;
                    float v0 = acc[mt][nt][half * 2];
                    float v1 = acc[mt][nt][half * 2 + 1];
                    __nv_bfloat16 h0 = __float2bfloat16(v0);
                    __nv_bfloat16 h1 = __float2bfloat16(v1);
                    __nv_bfloat162 hp, lp;
                    hp.x = h0; hp.y = h1;
                    lp.x = __float2bfloat16(v0 - __bfloat162float(h0));
                    lp.y = __float2bfloat16(v1 - __bfloat162float(h1));
                    size_t o = (size_t)row * 1024 + col;
                    *(__nv_bfloat162*)(Chi + o) = hp;
                    *(__nv_bfloat162*)(Clo + o) = lp;
                }
            }
        }
    }
}

// ---------------------------------------------------------------------------
// Masked softmax over scores rows -> row0. grid 64 (b*16+h), 256 threads.
// ---------------------------------------------------------------------------
__global__ __launch_bounds__(256) void softmax_kernel(const int* __restrict__ mask,
                                                      const float* __restrict__ scores,
                                                      float* __restrict__ row0)
{
    int bh = blockIdx.x;
    int b = bh >> 4;
    __shared__ float sc[1024];
    __shared__ float red[8];
    __shared__ float bc;
    int tid = threadIdx.x;

    float lmax = -3.4e38f;
#pragma unroll
    for (int it = 0; it < 4; it++) {
        int t = it * 256 + tid;
        float s = scores[(bh << 10) + t];
        s = (mask[b * 1024 + t] == 0) ? -1e9f : s;
        sc[t] = s;
        lmax = fmaxf(lmax, s);
    }
#pragma unroll
    for (int o = 16; o; o >>= 1) lmax = fmaxf(lmax, __shfl_xor_sync(0xffffffffu, lmax, o));
    if ((tid & 31) == 0) red[tid >> 5] = lmax;
    __syncthreads();
    if (tid == 0) {
        float m = red[0];
        for (int i = 1; i < 8; i++) m = fmaxf(m, red[i]);
        bc = m;
    }
    __syncthreads();
    float gmax = bc;

    float lsum = 0.f;
#pragma unroll
    for (int it = 0; it < 4; it++) {
        int t = it * 256 + tid;
        float e = expf(sc[t] - gmax);
        sc[t] = e;
        lsum += e;
    }
#pragma unroll
    for (int o = 16; o; o >>= 1) lsum += __shfl_xor_sync(0xffffffffu, lsum, o);
    if ((tid & 31) == 0) red[tid >> 5] = lsum;
    __syncthreads();
    if (tid == 0) {
        float s = 0.f;
        for (int i = 0; i < 8; i++) s += red[i];
        bc = 1.f / s;
    }
    __syncthreads();
    float invs = bc;
#pragma unroll
    for (int it = 0; it < 4; it++) {
        int t = it * 256 + tid;
        row0[(bh << 10) + t] = sc[t] * invs;
    }
}

// ---------------------------------------------------------------------------
// Conv1d(16 -> 1024, k=3, pad=1) + bias + relu
// ---------------------------------------------------------------------------
#define OPB 16
__global__ __launch_bounds__(256) void conv_kernel(const float* __restrict__ cw,
                                                   const float* __restrict__ cb,
                                                   const float* __restrict__ row0,
                                                   float* __restrict__ out)
{
    int lc = blockIdx.x, og = blockIdx.y, b = blockIdx.z;
    __shared__ float tile[16][264];
    __shared__ float ws[OPB * 48];
    __shared__ float wb[OPB];
    int tid = threadIdx.x;

    for (int idx = tid; idx < OPB * 48; idx += 256) {
        int o = og * OPB + idx / 48;
        ws[idx] = cw[o * 48 + (idx % 48)];
    }
    if (tid < OPB) wb[tid] = cb[og * OPB + tid];
    for (int idx = tid; idx < 16 * 258; idx += 256) {
        int c = idx / 258, x = idx % 258;
        int l = lc * 256 - 1 + x;
        tile[c][x] = (l >= 0 && l < SS) ? row0[((long long)(b * 16 + c)) * SS + l] : 0.f;
    }
    __syncthreads();

    float acc[OPB];
#pragma unroll
    for (int o = 0; o < OPB; o++) acc[o] = wb[o];
#pragma unroll
    for (int c = 0; c < 16; c++) {
        float r0 = tile[c][tid], r1 = tile[c][tid + 1], r2 = tile[c][tid + 2];
#pragma unroll
        for (int o = 0; o < OPB; o++) {
            acc[o] = fmaf(r0, ws[o * 48 + c * 3],     acc[o]);
            acc[o] = fmaf(r1, ws[o * 48 + c * 3 + 1], acc[o]);
            acc[o] = fmaf(r2, ws[o * 48 + c * 3 + 2], acc[o]);
        }
    }
    int l = lc * 256 + tid;
#pragma unroll
    for (int o = 0; o < OPB; o++)
        out[((long long)(b * 1024 + og * OPB + o)) * SS + l] = fmaxf(acc[o], 0.f);
}

// ---------------------------------------------------------------------------
extern "C" void kernel_launch(void* const* d_in, const int* in_sizes, int n_in,
                              void* d_out, int out_size)
{
    const float* X    = (const float*)d_in[0];
    const int*   mask = (const int*)d_in[1];
    const float* W_G  = (const float*)d_in[2];
    const float* b_G  = (const float*)d_in[3];
    const float* Wq   = (const float*)d_in[4];
    const float* bq   = (const float*)d_in[5];
    const float* Wk   = (const float*)d_in[6];
    const float* bk   = (const float*)d_in[7];
    const float* cw   = (const float*)d_in[8];
    const float* cb   = (const float*)d_in[9];
    float* out = (float*)d_out;

    __nv_bfloat16 *pXhi, *pXlo, *pWGhi, *pWGlo, *pWkThi, *pWkTlo, *pCThi, *pCTlo;
    float *pbiask, *pg0, *pq0, *pscores, *prow0;
    float2* ptab;
    cudaGetSymbolAddress((void**)&pXhi,    g_Xhi);
    cudaGetSymbolAddress((void**)&pXlo,    g_Xlo);
    cudaGetSymbolAddress((void**)&pWGhi,   g_WGhi);
    cudaGetSymbolAddress((void**)&pWGlo,   g_WGlo);
    cudaGetSymbolAddress((void**)&pWkThi,  g_WkThi);
    cudaGetSymbolAddress((void**)&pWkTlo,  g_WkTlo);
    cudaGetSymbolAddress((void**)&pCThi,   g_WGKThi);
    cudaGetSymbolAddress((void**)&pCTlo,   g_WGKTlo);
    cudaGetSymbolAddress((void**)&pbiask,  g_biask);
    cudaGetSymbolAddress((void**)&pg0,     g_g0);
    cudaGetSymbolAddress((void**)&pq0,     g_q0);
    cudaGetSymbolAddress((void**)&pscores, g_scores);
    cudaGetSymbolAddress((void**)&prow0,   g_row0);
    cudaGetSymbolAddress((void**)&ptab,    g_tab);

    static int smem_set = 0;
    if (!smem_set) {
        cudaFuncSetAttribute(mmagemm<128>, cudaFuncAttributeMaxDynamicSharedMemorySize, 132096);
        cudaFuncSetAttribute(mmagemm<64>,  cudaFuncAttributeMaxDynamicSharedMemorySize, 99328);
        smem_set = 1;
    }

    // RoPE table + small GEMVs
    tab_kernel<<<128, 256>>>(ptab);
    gemv_fast<<<dim3(16, 1), 256>>>(b_G, Wk, bk, pbiask, 0LL);
    gemv_fast<<<dim3(16, 4), 256>>>(X, W_G, b_G, pg0, (long long)SS * DD);
    gemv_fast<<<dim3(16, 4), 256>>>(pg0, Wq, bq, pq0, 1024LL);

    // Conversions
    split_kernel<<<4096, 256>>>((const float4*)X, (__nv_bfloat162*)pXhi,
                                (__nv_bfloat162*)pXlo, BB * SS * DD / 4);
    split_kernel<<<1024, 256>>>((const float4*)W_G, (__nv_bfloat162*)pWGhi,
                                (__nv_bfloat162*)pWGlo, DD * DD / 4);
    transpose_split_kernel<<<dim3(32, 32), dim3(32, 8)>>>(Wk, pWkThi, pWkTlo);

    // GEMM1: WGK^T (A = Wk^T, B = W_G), split-write bf16
    mmagemm<64><<<dim3(8, 16), 256, 99328>>>(pWkThi, pWkTlo, pWGhi, pWGlo, 0,
                                             nullptr, nullptr, nullptr, nullptr,
                                             pCThi, pCTlo);
    // GEMM2 fused: scores = q0 . rope(X @ WGK + biask) / 8
    mmagemm<128><<<dim3(8, 32), 256, 132096>>>(pXhi, pXlo, pCThi, pCTlo, 1,
                                               pbiask, pq0, ptab, pscores,
                                               nullptr, nullptr);

    softmax_kernel<<<64, 256>>>(mask, pscores, prow0);
    conv_kernel<<<dim3(4, 64, 4), 256>>>(cw, cb, prow0, out);
}

// round 13
// speedup vs baseline: 1.0331x; 1.0331x over previous
#include <cuda_runtime.h>
#include <cuda_bf16.h>
#include <cstdint>
#include <math.h>

#define BB 4
#define SS 1024
#define DD 1024
#define HH 16
#define DKK 64

// ---------------------------------------------------------------------------
// Portable PTX helpers (sm_80+: mma.sync bf16, ldmatrix, cp.async)
// ---------------------------------------------------------------------------
__device__ __forceinline__ uint32_t smem_u32(const void* p) {
    uint32_t a;
    asm("{ .reg .u64 t; cvta.to.shared.u64 t, %1; cvt.u32.u64 %0, t; }" : "=r"(a) : "l"(p));
    return a;
}
#define CPASYNC16(dst, src) \
    asm volatile("cp.async.cg.shared.global [%0], [%1], 16;" :: "r"(dst), "l"(src) : "memory")
#define CPCOMMIT() asm volatile("cp.async.commit_group;" ::: "memory")
#define CPWAITG(n) asm volatile("cp.async.wait_group %0;" :: "n"(n) : "memory")

#define LDSM4(r0, r1, r2, r3, addr) \
    asm volatile("ldmatrix.sync.aligned.m8n8.x4.shared.b16 {%0,%1,%2,%3}, [%4];" \
                 : "=r"(r0), "=r"(r1), "=r"(r2), "=r"(r3) : "r"(addr))

#define MMA16816(c, a, b) \
    asm volatile("mma.sync.aligned.m16n8k16.row.col.f32.bf16.bf16.f32 " \
                 "{%0,%1,%2,%3},{%4,%5,%6,%7},{%8,%9},{%0,%1,%2,%3};" \
                 : "+f"((c)[0]), "+f"((c)[1]), "+f"((c)[2]), "+f"((c)[3]) \
                 : "r"((a)[0]), "r"((a)[1]), "r"((a)[2]), "r"((a)[3]), \
                   "r"((b)[0]), "r"((b)[1]))

// ---------------------------------------------------------------------------
// Scratch (static device globals)
// ---------------------------------------------------------------------------
__device__ __nv_bfloat16 g_Xhi[BB * SS * DD];
__device__ __nv_bfloat16 g_Xlo[BB * SS * DD];
__device__ __nv_bfloat16 g_WGhi[DD * DD];
__device__ __nv_bfloat16 g_WGlo[DD * DD];
__device__ __nv_bfloat16 g_WkThi[DD * DD];
__device__ __nv_bfloat16 g_WkTlo[DD * DD];
__device__ __nv_bfloat16 g_WGKThi[DD * DD];
__device__ __nv_bfloat16 g_WGKTlo[DD * DD];
__device__ float  g_biask[DD];
__device__ float  g_g0[BB * DD];
__device__ float  g_q0[BB * DD];
__device__ float  g_scores[BB * HH * SS];
__device__ float  g_row0[BB * HH * SS];
__device__ float2 g_tab[SS * 32];          // (cos, sin) for pos t, freq p

// ---------------------------------------------------------------------------
// RoPE sincos table: tab[t*32+p] = (cos(t*inv_p), sin(t*inv_p))
// ---------------------------------------------------------------------------
__global__ void tab_kernel(float2* __restrict__ tab)
{
    int idx = blockIdx.x * 256 + threadIdx.x;   // 32768 total
    int t = idx >> 5, p = idx & 31;
    float inv = exp2f(-(float)p * 0.41524101186092029f);  // 10000^(-p/32)
    float sn, cs;
    sincosf((float)t * inv, &sn, &cs);
    tab[idx] = make_float2(cs, sn);
}

// ---------------------------------------------------------------------------
// fp32 -> bf16 hi/lo split
// ---------------------------------------------------------------------------
__global__ void split_kernel(const float4* __restrict__ in,
                             __nv_bfloat162* __restrict__ hi,
                             __nv_bfloat162* __restrict__ lo, int n4)
{
    int i = blockIdx.x * 256 + threadIdx.x;
    if (i >= n4) return;
    float4 v = in[i];
    __nv_bfloat16 hx = __float2bfloat16(v.x), hy = __float2bfloat16(v.y);
    __nv_bfloat16 hz = __float2bfloat16(v.z), hw = __float2bfloat16(v.w);
    __nv_bfloat162 a, b;
    a.x = hx; a.y = hy; b.x = hz; b.y = hw;
    hi[2 * i] = a; hi[2 * i + 1] = b;
    __nv_bfloat162 c, d;
    c.x = __float2bfloat16(v.x - __bfloat162float(hx));
    c.y = __float2bfloat16(v.y - __bfloat162float(hy));
    d.x = __float2bfloat16(v.z - __bfloat162float(hz));
    d.y = __float2bfloat16(v.w - __bfloat162float(hw));
    lo[2 * i] = c; lo[2 * i + 1] = d;
}

// Transpose + split: out[c][r] = in[r][c], 1024x1024
__global__ void transpose_split_kernel(const float* __restrict__ in,
                                       __nv_bfloat16* __restrict__ thi,
                                       __nv_bfloat16* __restrict__ tlo)
{
    __shared__ float t[32][33];
    int c0 = blockIdx.x * 32, r0 = blockIdx.y * 32;
    int tx = threadIdx.x, ty = threadIdx.y;
#pragma unroll
    for (int k = 0; k < 4; k++)
        t[ty + 8 * k][tx] = in[(size_t)(r0 + ty + 8 * k) * 1024 + c0 + tx];
    __syncthreads();
#pragma unroll
    for (int k = 0; k < 4; k++) {
        float v = t[tx][ty + 8 * k];
        __nv_bfloat16 h = __float2bfloat16(v);
        size_t o = (size_t)(c0 + ty + 8 * k) * 1024 + r0 + tx;
        thi[o] = h;
        tlo[o] = __float2bfloat16(v - __bfloat162float(h));
    }
}

// ---------------------------------------------------------------------------
// Fast GEMV (round-10 version): 1 col/lane, 32 cols/block, grid (32, nb).
// ---------------------------------------------------------------------------
__global__ __launch_bounds__(256) void gemv_fast(const float* __restrict__ x,
                                                 const float* __restrict__ W,
                                                 const float* __restrict__ bv,
                                                 float* __restrict__ out,
                                                 long long xstride)
{
    __shared__ float xs[1024];
    __shared__ float red[8][32];
    const int b = blockIdx.y;
    const int tid = threadIdx.x;
    const int lane = tid & 31, ig = tid >> 5;
    const float* xr = x + (long long)b * xstride;
    for (int i = tid; i < 1024; i += 256) xs[i] = xr[i];
    __syncthreads();

    const int j = blockIdx.x * 32 + lane;
    const float* Wp = W + (long long)(ig * 128) * 1024 + j;
    float a0 = 0.f;
#pragma unroll 8
    for (int i = 0; i < 128; i++)
        a0 = fmaf(xs[ig * 128 + i], Wp[(long long)i * 1024], a0);
    red[ig][lane] = a0;
    __syncthreads();
    if (tid < 32) {
        int jo = blockIdx.x * 32 + tid;
        float s = bv[jo];
#pragma unroll
        for (int g = 0; g < 8; g++) s += red[g][tid];
        out[b * 1024 + jo] = s;
    }
}

// ---------------------------------------------------------------------------
// mma.sync bf16 GEMM (round-10 version): 3-term hi/lo split, CTA MTILE x 128,
// 8 warps, K chunks of 32, 3-stage cp.async pipeline, SW128 swizzle.
// mode 0: split-write bf16 Chi/Clo
// mode 1 (MTILE=128 only): scores[b,h,t] = q0[b,h,:] . rope_t(v + bias) / 8
// ---------------------------------------------------------------------------
template <int MTILE>
__global__ __launch_bounds__(256) void mmagemm(
    const __nv_bfloat16* __restrict__ Ahi, const __nv_bfloat16* __restrict__ Alo,
    const __nv_bfloat16* __restrict__ Bhi, const __nv_bfloat16* __restrict__ Blo,
    int mode,
    const float* __restrict__ bias, const float* __restrict__ q0,
    const float2* __restrict__ tab, float* __restrict__ scores,
    __nv_bfloat16* __restrict__ Chi, __nv_bfloat16* __restrict__ Clo)
{
    constexpr int MT = MTILE / 32;               // m-subtiles per warp
    constexpr int AIT = MTILE / 32;              // A cp.async tasks per thread
    constexpr uint32_t STAGE = (MTILE + 128) * 128;
    constexpr uint32_t BOFF = MTILE * 128;

    extern __shared__ char dyn[];
    uint32_t dynb = smem_u32(dyn);
    const uint32_t sbase = (dynb + 1023) & ~1023u;   // 1KB-aligned smem base

    const int tid = threadIdx.x;
    const int wid = tid >> 5, lane = tid & 31;
    const int gid = lane >> 2, tig = lane & 3;
    const int m0 = blockIdx.y * MTILE, n0 = blockIdx.x * 128;
    const int wm = (wid >> 2) * (MTILE / 2);    // warp m offset
    const int wn = (wid & 3) * 32;              // warp n offset (0..96)

    // ---- cp.async task precompute ------------------------------------------
    const __nv_bfloat16* aSrc[AIT];
    const __nv_bfloat16* bSrc[4];
    uint32_t aDst[AIT], bDst[4];
#pragma unroll
    for (int it = 0; it < AIT; it++) {
        int ix = it * 256 + tid;
        int r = ix >> 3, seg = ix & 7;      // r: row ; seg: 16B segment
        const __nv_bfloat16* ah = (seg < 4) ? Ahi : Alo;
        aSrc[it] = ah + (size_t)(m0 + r) * 1024 + (seg & 3) * 8;
        aDst[it] = sbase + r * 128 + ((seg * 16) ^ ((r & 7) << 4));
    }
#pragma unroll
    for (int it = 0; it < 4; it++) {
        int ix = it * 256 + tid;
        int r = ix >> 3, seg = ix & 7;
        const __nv_bfloat16* bh = (seg < 4) ? Bhi : Blo;
        bSrc[it] = bh + (size_t)(n0 + r) * 1024 + (seg & 3) * 8;
        bDst[it] = sbase + BOFF + r * 128 + ((seg * 16) ^ ((r & 7) << 4));
    }

    // ---- ldmatrix address precompute ---------------------------------------
    const uint32_t xorv = (lane & 7) << 4;          // swizzle XOR (const/thread)
    const uint32_t ksel = (lane >> 4) * 16;         // k-half selector
    uint32_t aRow[MT], bRow[2];
#pragma unroll
    for (int mt = 0; mt < MT; mt++) aRow[mt] = (wm + mt * 16 + (lane & 15)) * 128;
#pragma unroll
    for (int ng = 0; ng < 2; ng++)  bRow[ng] = BOFF + (wn + ng * 16 + (lane & 15)) * 128;

    float acc[MT][4][4];
#pragma unroll
    for (int mt = 0; mt < MT; mt++)
#pragma unroll
        for (int nt = 0; nt < 4; nt++)
#pragma unroll
            for (int i = 0; i < 4; i++) acc[mt][nt][i] = 0.f;

    // ---- prologue: chunks 0,1 into stages 0,1 ------------------------------
#pragma unroll
    for (int pre = 0; pre < 2; pre++) {
        const uint32_t so = pre * STAGE;
        const int ko = pre * 32;
#pragma unroll
        for (int it = 0; it < AIT; it++) CPASYNC16(aDst[it] + so, aSrc[it] + ko);
#pragma unroll
        for (int it = 0; it < 4; it++)   CPASYNC16(bDst[it] + so, bSrc[it] + ko);
        CPCOMMIT();
    }

    uint32_t snext = 2 * STAGE;          // stage rotation: 0,1,2,0,...
#pragma unroll 1
    for (int ch = 0; ch < 32; ch++) {
        if (ch < 30) {
            const int ko = (ch + 2) * 32;
#pragma unroll
            for (int it = 0; it < AIT; it++) CPASYNC16(aDst[it] + snext, aSrc[it] + ko);
#pragma unroll
            for (int it = 0; it < 4; it++)   CPASYNC16(bDst[it] + snext, bSrc[it] + ko);
            CPCOMMIT();
            CPWAITG(2);
        } else if (ch == 30) {
            CPWAITG(1);
        } else {
            CPWAITG(0);
        }
        __syncthreads();

        const uint32_t As = sbase + (ch % 3) * STAGE;
        snext = As;                      // stage just consumed = next to fill
#pragma unroll
        for (int ks = 0; ks < 2; ks++) {
            const uint32_t khi = (ks * 32 + ksel) ^ xorv;
            const uint32_t klo = (64 + ks * 32 + ksel) ^ xorv;
            uint32_t ah[MT][4], al[MT][4], bh[4][2], bl[4][2];
#pragma unroll
            for (int mt = 0; mt < MT; mt++) {
                LDSM4(ah[mt][0], ah[mt][1], ah[mt][2], ah[mt][3], As + aRow[mt] + khi);
                LDSM4(al[mt][0], al[mt][1], al[mt][2], al[mt][3], As + aRow[mt] + klo);
            }
#pragma unroll
            for (int ng = 0; ng < 2; ng++) {
                uint32_t r0, r1, r2, r3;
                LDSM4(r0, r1, r2, r3, As + bRow[ng] + khi);
                bh[2 * ng][0] = r0; bh[2 * ng][1] = r2;
                bh[2 * ng + 1][0] = r1; bh[2 * ng + 1][1] = r3;
                LDSM4(r0, r1, r2, r3, As + bRow[ng] + klo);
                bl[2 * ng][0] = r0; bl[2 * ng][1] = r2;
                bl[2 * ng + 1][0] = r1; bl[2 * ng + 1][1] = r3;
            }
#pragma unroll
            for (int mt = 0; mt < MT; mt++)
#pragma unroll
                for (int nt = 0; nt < 4; nt++) {
                    MMA16816(acc[mt][nt], ah[mt], bh[nt]);
                    MMA16816(acc[mt][nt], ah[mt], bl[nt]);
                    MMA16816(acc[mt][nt], al[mt], bh[nt]);
                }
        }
        __syncthreads();
        snext -= sbase;                  // back to byte offset for cp.async
    }

    // ---- epilogue ----------------------------------------------------------
    if (mode == 1) {
        // Fused: rope(v+bias), dot with q0, reduce -> scores[b, h, t]
        const int b = m0 >> 10;
        const int tbase = m0 & 1023;
        float2 bb[4], qv[4];
        const float2* tabp[4];
#pragma unroll
        for (int nt = 0; nt < 4; nt++) {
            int col = n0 + wn + nt * 8 + 2 * tig;
            bb[nt] = *(const float2*)(bias + col);
            qv[nt] = *(const float2*)(q0 + b * 1024 + col);
            tabp[nt] = tab + ((col & 63) >> 1);
        }
        float* spart = (float*)dyn;      // [MTILE][4] partials
#pragma unroll
        for (int mt = 0; mt < MT; mt++) {
#pragma unroll
            for (int half = 0; half < 2; half++) {
                int rl = wm + mt * 16 + gid + half * 8;      // local row
                int t = tbase + rl;
                float p_acc = 0.f;
#pragma unroll
                for (int nt = 0; nt < 4; nt++) {
                    float2 cssn = tabp[nt][t * 32];
                    float v0 = acc[mt][nt][half * 2]     + bb[nt].x;
                    float v1 = acc[mt][nt][half * 2 + 1] + bb[nt].y;
                    float kw0 = v0 * cssn.x - v1 * cssn.y;
                    float kw1 = v1 * cssn.x + v0 * cssn.y;
                    p_acc = fmaf(qv[nt].x, kw0, p_acc);
                    p_acc = fmaf(qv[nt].y, kw1, p_acc);
                }
                p_acc += __shfl_xor_sync(0xffffffffu, p_acc, 1);
                p_acc += __shfl_xor_sync(0xffffffffu, p_acc, 2);
                if (tig == 0) spart[rl * 4 + (wn >> 5)] = p_acc;
            }
        }
        __syncthreads();
        if (tid < MTILE) {
            int t = tbase + tid;
            float s0 = (spart[tid * 4 + 0] + spart[tid * 4 + 1]) * 0.125f;
            float s1 = (spart[tid * 4 + 2] + spart[tid * 4 + 3]) * 0.125f;
            int h0 = n0 >> 6;
            scores[((b * 16 + h0)     << 10) + t] = s0;
            scores[((b * 16 + h0 + 1) << 10) + t] = s1;
        }
    } else {
#pragma unroll
        for (int mt = 0; mt < MT; mt++) {
#pragma unroll
            for (int half = 0; half < 2; half++) {
                int row = m0 + wm + mt * 16 + gid + half * 8;
#pragma unroll
                for (int nt = 0; nt < 4; nt++) {
                    int col = n0 + wn + nt * 8 + 2 * tig;
                    float v0 = acc[mt][nt][half * 2];
                    float v1 = acc[mt][nt][half * 2 + 1];
                    __nv_bfloat16 h0 = __float2bfloat16(v0);
                    __nv_bfloat16 h1 = __float2bfloat16(v1);
                    __nv_bfloat162 hp, lp;
                    hp.x = h0; hp.y = h1;
                    lp.x = __float2bfloat16(v0 - __bfloat162float(h0));
                    lp.y = __float2bfloat16(v1 - __bfloat162float(h1));
                    size_t o = (size_t)row * 1024 + col;
                    *(__nv_bfloat162*)(Chi + o) = hp;
                    *(__nv_bfloat162*)(Clo + o) = lp;
                }
            }
        }
    }
}

// ---------------------------------------------------------------------------
// Masked softmax over scores rows -> row0. grid 64 (b*16+h), 256 threads.
// ---------------------------------------------------------------------------
__global__ __launch_bounds__(256) void softmax_kernel(const int* __restrict__ mask,
                                                      const float* __restrict__ scores,
                                                      float* __restrict__ row0)
{
    int bh = blockIdx.x;
    int b = bh >> 4;
    __shared__ float sc[1024];
    __shared__ float red[8];
    __shared__ float bc;
    int tid = threadIdx.x;

    float lmax = -3.4e38f;
#pragma unroll
    for (int it = 0; it < 4; it++) {
        int t = it * 256 + tid;
        float s = scores[(bh << 10) + t];
        s = (mask[b * 1024 + t] == 0) ? -1e9f : s;
        sc[t] = s;
        lmax = fmaxf(lmax, s);
    }
#pragma unroll
    for (int o = 16; o; o >>= 1) lmax = fmaxf(lmax, __shfl_xor_sync(0xffffffffu, lmax, o));
    if ((tid & 31) == 0) red[tid >> 5] = lmax;
    __syncthreads();
    if (tid == 0) {
        float m = red[0];
        for (int i = 1; i < 8; i++) m = fmaxf(m, red[i]);
        bc = m;
    }
    __syncthreads();
    float gmax = bc;

    float lsum = 0.f;
#pragma unroll
    for (int it = 0; it < 4; it++) {
        int t = it * 256 + tid;
        float e = expf(sc[t] - gmax);
        sc[t] = e;
        lsum += e;
    }
#pragma unroll
    for (int o = 16; o; o >>= 1) lsum += __shfl_xor_sync(0xffffffffu, lsum, o);
    if ((tid & 31) == 0) red[tid >> 5] = lsum;
    __syncthreads();
    if (tid == 0) {
        float s = 0.f;
        for (int i = 0; i < 8; i++) s += red[i];
        bc = 1.f / s;
    }
    __syncthreads();
    float invs = bc;
#pragma unroll
    for (int it = 0; it < 4; it++) {
        int t = it * 256 + tid;
        row0[(bh << 10) + t] = sc[t] * invs;
    }
}

// ---------------------------------------------------------------------------
// Conv1d(16 -> 1024, k=3, pad=1) + bias + relu
// ---------------------------------------------------------------------------
#define OPB 16
__global__ __launch_bounds__(256) void conv_kernel(const float* __restrict__ cw,
                                                   const float* __restrict__ cb,
                                                   const float* __restrict__ row0,
                                                   float* __restrict__ out)
{
    int lc = blockIdx.x, og = blockIdx.y, b = blockIdx.z;
    __shared__ float tile[16][264];
    __shared__ float ws[OPB * 48];
    __shared__ float wb[OPB];
    int tid = threadIdx.x;

    for (int idx = tid; idx < OPB * 48; idx += 256) {
        int o = og * OPB + idx / 48;
        ws[idx] = cw[o * 48 + (idx % 48)];
    }
    if (tid < OPB) wb[tid] = cb[og * OPB + tid];
    for (int idx = tid; idx < 16 * 258; idx += 256) {
        int c = idx / 258, x = idx % 258;
        int l = lc * 256 - 1 + x;
        tile[c][x] = (l >= 0 && l < SS) ? row0[((long long)(b * 16 + c)) * SS + l] : 0.f;
    }
    __syncthreads();

    float acc[OPB];
#pragma unroll
    for (int o = 0; o < OPB; o++) acc[o] = wb[o];
#pragma unroll
    for (int c = 0; c < 16; c++) {
        float r0 = tile[c][tid], r1 = tile[c][tid + 1], r2 = tile[c][tid + 2];
#pragma unroll
        for (int o = 0; o < OPB; o++) {
            acc[o] = fmaf(r0, ws[o * 48 + c * 3],     acc[o]);
            acc[o] = fmaf(r1, ws[o * 48 + c * 3 + 1], acc[o]);
            acc[o] = fmaf(r2, ws[o * 48 + c * 3 + 2], acc[o]);
        }
    }
    int l = lc * 256 + tid;
#pragma unroll
    for (int o = 0; o < OPB; o++)
        out[((long long)(b * 1024 + og * OPB + o)) * SS + l] = fmaxf(acc[o], 0.f);
}

// ---------------------------------------------------------------------------
extern "C" void kernel_launch(void* const* d_in, const int* in_sizes, int n_in,
                              void* d_out, int out_size)
{
    const float* X    = (const float*)d_in[0];
    const int*   mask = (const int*)d_in[1];
    const float* W_G  = (const float*)d_in[2];
    const float* b_G  = (const float*)d_in[3];
    const float* Wq   = (const float*)d_in[4];
    const float* bq   = (const float*)d_in[5];
    const float* Wk   = (const float*)d_in[6];
    const float* bk   = (const float*)d_in[7];
    const float* cw   = (const float*)d_in[8];
    const float* cb   = (const float*)d_in[9];
    float* out = (float*)d_out;

    __nv_bfloat16 *pXhi, *pXlo, *pWGhi, *pWGlo, *pWkThi, *pWkTlo, *pCThi, *pCTlo;
    float *pbiask, *pg0, *pq0, *pscores, *prow0;
    float2* ptab;
    cudaGetSymbolAddress((void**)&pXhi,    g_Xhi);
    cudaGetSymbolAddress((void**)&pXlo,    g_Xlo);
    cudaGetSymbolAddress((void**)&pWGhi,   g_WGhi);
    cudaGetSymbolAddress((void**)&pWGlo,   g_WGlo);
    cudaGetSymbolAddress((void**)&pWkThi,  g_WkThi);
    cudaGetSymbolAddress((void**)&pWkTlo,  g_WkTlo);
    cudaGetSymbolAddress((void**)&pCThi,   g_WGKThi);
    cudaGetSymbolAddress((void**)&pCTlo,   g_WGKTlo);
    cudaGetSymbolAddress((void**)&pbiask,  g_biask);
    cudaGetSymbolAddress((void**)&pg0,     g_g0);
    cudaGetSymbolAddress((void**)&pq0,     g_q0);
    cudaGetSymbolAddress((void**)&pscores, g_scores);
    cudaGetSymbolAddress((void**)&prow0,   g_row0);
    cudaGetSymbolAddress((void**)&ptab,    g_tab);

    // One-time resource setup (runs on the uncaptured correctness call; no
    // device memory is allocated — streams/events only).
    static int inited = 0;
    static cudaStream_t sA, sB, sC;
    static cudaEvent_t evRoot, evA, evB, evC;
    if (!inited) {
        cudaFuncSetAttribute(mmagemm<128>, cudaFuncAttributeMaxDynamicSharedMemorySize, 99328);
        cudaFuncSetAttribute(mmagemm<64>,  cudaFuncAttributeMaxDynamicSharedMemorySize, 74752);
        cudaStreamCreateWithFlags(&sA, cudaStreamNonBlocking);
        cudaStreamCreateWithFlags(&sB, cudaStreamNonBlocking);
        cudaStreamCreateWithFlags(&sC, cudaStreamNonBlocking);
        cudaEventCreateWithFlags(&evRoot, cudaEventDisableTiming);
        cudaEventCreateWithFlags(&evA, cudaEventDisableTiming);
        cudaEventCreateWithFlags(&evB, cudaEventDisableTiming);
        cudaEventCreateWithFlags(&evC, cudaEventDisableTiming);
        inited = 1;
    }

    // ---- fork: three side streams off the main (capture) stream -----------
    cudaEventRecord(evRoot, 0);
    cudaStreamWaitEvent(sA, evRoot, 0);
    cudaStreamWaitEvent(sB, evRoot, 0);
    cudaStreamWaitEvent(sC, evRoot, 0);

    // sA: the dependent GEMV chain  g0 = X0@W_G + b_G ; q0 = g0@Wq + bq
    gemv_fast<<<dim3(32, 4), 256, 0, sA>>>(X, W_G, b_G, pg0, (long long)SS * DD);
    gemv_fast<<<dim3(32, 4), 256, 0, sA>>>(pg0, Wq, bq, pq0, 1024LL);
    cudaEventRecord(evA, sA);

    // sC: rope table + biask = b_G@Wk + bk (independent)
    tab_kernel<<<128, 256, 0, sC>>>(ptab);
    gemv_fast<<<dim3(32, 1), 256, 0, sC>>>(b_G, Wk, bk, pbiask, 0LL);
    cudaEventRecord(evC, sC);

    // sB: weight conversions + GEMM1 (WGK^T = (Wk^T)(W_G^T) split-write bf16)
    split_kernel<<<1024, 256, 0, sB>>>((const float4*)W_G, (__nv_bfloat162*)pWGhi,
                                       (__nv_bfloat162*)pWGlo, DD * DD / 4);
    transpose_split_kernel<<<dim3(32, 32), dim3(32, 8), 0, sB>>>(Wk, pWkThi, pWkTlo);
    mmagemm<64><<<dim3(8, 16), 256, 74752, sB>>>(pWkThi, pWkTlo, pWGhi, pWGlo, 0,
                                                 nullptr, nullptr, nullptr, nullptr,
                                                 pCThi, pCTlo);
    cudaEventRecord(evB, sB);

    // main stream: X split (big; runs concurrently with the forks)
    split_kernel<<<4096, 256>>>((const float4*)X, (__nv_bfloat162*)pXhi,
                                (__nv_bfloat162*)pXlo, BB * SS * DD / 4);

    // ---- join on main ------------------------------------------------------
    cudaStreamWaitEvent(0, evA, 0);
    cudaStreamWaitEvent(0, evB, 0);
    cudaStreamWaitEvent(0, evC, 0);

    // GEMM2 fused: scores = q0 . rope(X @ WGK + biask) / 8
    mmagemm<128><<<dim3(8, 32), 256, 99328>>>(pXhi, pXlo, pCThi, pCTlo, 1,
                                              pbiask, pq0, ptab, pscores,
                                              nullptr, nullptr);

    softmax_kernel<<<64, 256>>>(mask, pscores, prow0);
    conv_kernel<<<dim3(4, 64, 4), 256>>>(cw, cb, prow0, out);
}

// round 14
// speedup vs baseline: 1.0620x; 1.0280x over previous
#include <cuda_runtime.h>
#include <cuda_bf16.h>
#include <cstdint>
#include <math.h>

#define BB 4
#define SS 1024
#define DD 1024
#define HH 16
#define DKK 64

// ---------------------------------------------------------------------------
// Portable PTX helpers (sm_80+: mma.sync bf16, ldmatrix, cp.async)
// ---------------------------------------------------------------------------
__device__ __forceinline__ uint32_t smem_u32(const void* p) {
    uint32_t a;
    asm("{ .reg .u64 t; cvta.to.shared.u64 t, %1; cvt.u32.u64 %0, t; }" : "=r"(a) : "l"(p));
    return a;
}
#define CPASYNC16(dst, src) \
    asm volatile("cp.async.cg.shared.global [%0], [%1], 16;" :: "r"(dst), "l"(src) : "memory")
#define CPCOMMIT() asm volatile("cp.async.commit_group;" ::: "memory")
#define CPWAITG(n) asm volatile("cp.async.wait_group %0;" :: "n"(n) : "memory")

#define LDSM4(r0, r1, r2, r3, addr) \
    asm volatile("ldmatrix.sync.aligned.m8n8.x4.shared.b16 {%0,%1,%2,%3}, [%4];" \
                 : "=r"(r0), "=r"(r1), "=r"(r2), "=r"(r3) : "r"(addr))

#define MMA16816(c, a, b) \
    asm volatile("mma.sync.aligned.m16n8k16.row.col.f32.bf16.bf16.f32 " \
                 "{%0,%1,%2,%3},{%4,%5,%6,%7},{%8,%9},{%0,%1,%2,%3};" \
                 : "+f"((c)[0]), "+f"((c)[1]), "+f"((c)[2]), "+f"((c)[3]) \
                 : "r"((a)[0]), "r"((a)[1]), "r"((a)[2]), "r"((a)[3]), \
                   "r"((b)[0]), "r"((b)[1]))

// ---------------------------------------------------------------------------
// Scratch (static device globals)
// ---------------------------------------------------------------------------
__device__ __nv_bfloat16 g_Xhi[BB * SS * DD];
__device__ __nv_bfloat16 g_Xlo[BB * SS * DD];
__device__ __nv_bfloat16 g_WGhi[DD * DD];
__device__ __nv_bfloat16 g_WGlo[DD * DD];
__device__ __nv_bfloat16 g_WkThi[DD * DD];
__device__ __nv_bfloat16 g_WkTlo[DD * DD];
__device__ __nv_bfloat16 g_WGKThi[DD * DD];
__device__ __nv_bfloat16 g_WGKTlo[DD * DD];
__device__ float  g_biask[DD];
__device__ float  g_g0[BB * DD];
__device__ float  g_q0[BB * DD];
__device__ float  g_scores[BB * HH * SS];
__device__ float  g_row0[BB * HH * SS];
__device__ float2 g_tab[SS * 32];          // (cos, sin) for pos t, freq p

// ---------------------------------------------------------------------------
// RoPE sincos table: tab[t*32+p] = (cos(t*inv_p), sin(t*inv_p))
// ---------------------------------------------------------------------------
__global__ void tab_kernel(float2* __restrict__ tab)
{
    int idx = blockIdx.x * 256 + threadIdx.x;   // 32768 total
    int t = idx >> 5, p = idx & 31;
    float inv = exp2f(-(float)p * 0.41524101186092029f);  // 10000^(-p/32)
    float sn, cs;
    sincosf((float)t * inv, &sn, &cs);
    tab[idx] = make_float2(cs, sn);
}

// ---------------------------------------------------------------------------
// fp32 -> bf16 hi/lo split
// ---------------------------------------------------------------------------
__global__ void split_kernel(const float4* __restrict__ in,
                             __nv_bfloat162* __restrict__ hi,
                             __nv_bfloat162* __restrict__ lo, int n4)
{
    int i = blockIdx.x * 256 + threadIdx.x;
    if (i >= n4) return;
    float4 v = in[i];
    __nv_bfloat16 hx = __float2bfloat16(v.x), hy = __float2bfloat16(v.y);
    __nv_bfloat16 hz = __float2bfloat16(v.z), hw = __float2bfloat16(v.w);
    __nv_bfloat162 a, b;
    a.x = hx; a.y = hy; b.x = hz; b.y = hw;
    hi[2 * i] = a; hi[2 * i + 1] = b;
    __nv_bfloat162 c, d;
    c.x = __float2bfloat16(v.x - __bfloat162float(hx));
    c.y = __float2bfloat16(v.y - __bfloat162float(hy));
    d.x = __float2bfloat16(v.z - __bfloat162float(hz));
    d.y = __float2bfloat16(v.w - __bfloat162float(hw));
    lo[2 * i] = c; lo[2 * i + 1] = d;
}

// Transpose + split: out[c][r] = in[r][c], 1024x1024
__global__ void transpose_split_kernel(const float* __restrict__ in,
                                       __nv_bfloat16* __restrict__ thi,
                                       __nv_bfloat16* __restrict__ tlo)
{
    __shared__ float t[32][33];
    int c0 = blockIdx.x * 32, r0 = blockIdx.y * 32;
    int tx = threadIdx.x, ty = threadIdx.y;
#pragma unroll
    for (int k = 0; k < 4; k++)
        t[ty + 8 * k][tx] = in[(size_t)(r0 + ty + 8 * k) * 1024 + c0 + tx];
    __syncthreads();
#pragma unroll
    for (int k = 0; k < 4; k++) {
        float v = t[tx][ty + 8 * k];
        __nv_bfloat16 h = __float2bfloat16(v);
        size_t o = (size_t)(c0 + ty + 8 * k) * 1024 + r0 + tx;
        thi[o] = h;
        tlo[o] = __float2bfloat16(v - __bfloat162float(h));
    }
}

// ---------------------------------------------------------------------------
// Fast GEMV: 1 col/lane, 32 cols/block, grid (32, nb).
// ---------------------------------------------------------------------------
__global__ __launch_bounds__(256) void gemv_fast(const float* __restrict__ x,
                                                 const float* __restrict__ W,
                                                 const float* __restrict__ bv,
                                                 float* __restrict__ out,
                                                 long long xstride)
{
    __shared__ float xs[1024];
    __shared__ float red[8][32];
    const int b = blockIdx.y;
    const int tid = threadIdx.x;
    const int lane = tid & 31, ig = tid >> 5;
    const float* xr = x + (long long)b * xstride;
    for (int i = tid; i < 1024; i += 256) xs[i] = xr[i];
    __syncthreads();

    const int j = blockIdx.x * 32 + lane;
    const float* Wp = W + (long long)(ig * 128) * 1024 + j;
    float a0 = 0.f;
#pragma unroll 8
    for (int i = 0; i < 128; i++)
        a0 = fmaf(xs[ig * 128 + i], Wp[(long long)i * 1024], a0);
    red[ig][lane] = a0;
    __syncthreads();
    if (tid < 32) {
        int jo = blockIdx.x * 32 + tid;
        float s = bv[jo];
#pragma unroll
        for (int g = 0; g < 8; g++) s += red[g][tid];
        out[b * 1024 + jo] = s;
    }
}

// ---------------------------------------------------------------------------
// mma.sync bf16 GEMM: 3-term hi/lo split, CTA MTILE x 128, 8 warps,
// K chunks of 32, TWO-stage cp.async pipeline, __launch_bounds__(256, 2)
// => 2 CTAs/SM, 16 warps/SM (GEMM2: 256 CTAs = ONE wave at 296 slots).
// Inner loop restructured B-first / A-just-in-time to keep regs <= 128.
// mode 0: split-write bf16 Chi/Clo
// mode 1 (MTILE=128 only): scores[b,h,t] = q0[b,h,:] . rope_t(v + bias) / 8
// ---------------------------------------------------------------------------
template <int MTILE>
__global__ __launch_bounds__(256, 2) void mmagemm(
    const __nv_bfloat16* __restrict__ Ahi, const __nv_bfloat16* __restrict__ Alo,
    const __nv_bfloat16* __restrict__ Bhi, const __nv_bfloat16* __restrict__ Blo,
    int mode,
    const float* __restrict__ bias, const float* __restrict__ q0,
    const float2* __restrict__ tab, float* __restrict__ scores,
    __nv_bfloat16* __restrict__ Chi, __nv_bfloat16* __restrict__ Clo)
{
    constexpr int MT = MTILE / 32;               // m-subtiles per warp
    constexpr int AIT = MTILE / 32;              // A cp.async tasks per thread
    constexpr uint32_t STAGE = (MTILE + 128) * 128;
    constexpr uint32_t BOFF = MTILE * 128;

    extern __shared__ char dyn[];
    uint32_t dynb = smem_u32(dyn);
    const uint32_t sbase = (dynb + 1023) & ~1023u;   // 1KB-aligned smem base

    const int tid = threadIdx.x;
    const int wid = tid >> 5, lane = tid & 31;
    const int gid = lane >> 2, tig = lane & 3;
    const int m0 = blockIdx.y * MTILE, n0 = blockIdx.x * 128;
    const int wm = (wid >> 2) * (MTILE / 2);    // warp m offset
    const int wn = (wid & 3) * 32;              // warp n offset (0..96)

    // ---- cp.async task precompute ------------------------------------------
    const __nv_bfloat16* aSrc[AIT];
    const __nv_bfloat16* bSrc[4];
    uint32_t aDst[AIT], bDst[4];
#pragma unroll
    for (int it = 0; it < AIT; it++) {
        int ix = it * 256 + tid;
        int r = ix >> 3, seg = ix & 7;      // r: row ; seg: 16B segment
        const __nv_bfloat16* ah = (seg < 4) ? Ahi : Alo;
        aSrc[it] = ah + (size_t)(m0 + r) * 1024 + (seg & 3) * 8;
        aDst[it] = sbase + r * 128 + ((seg * 16) ^ ((r & 7) << 4));
    }
#pragma unroll
    for (int it = 0; it < 4; it++) {
        int ix = it * 256 + tid;
        int r = ix >> 3, seg = ix & 7;
        const __nv_bfloat16* bh = (seg < 4) ? Bhi : Blo;
        bSrc[it] = bh + (size_t)(n0 + r) * 1024 + (seg & 3) * 8;
        bDst[it] = sbase + BOFF + r * 128 + ((seg * 16) ^ ((r & 7) << 4));
    }

    // ---- ldmatrix address precompute ---------------------------------------
    const uint32_t xorv = (lane & 7) << 4;          // swizzle XOR (const/thread)
    const uint32_t ksel = (lane >> 4) * 16;         // k-half selector
    uint32_t aRow[MT], bRow[2];
#pragma unroll
    for (int mt = 0; mt < MT; mt++) aRow[mt] = (wm + mt * 16 + (lane & 15)) * 128;
#pragma unroll
    for (int ng = 0; ng < 2; ng++)  bRow[ng] = BOFF + (wn + ng * 16 + (lane & 15)) * 128;

    float acc[MT][4][4];
#pragma unroll
    for (int mt = 0; mt < MT; mt++)
#pragma unroll
        for (int nt = 0; nt < 4; nt++)
#pragma unroll
            for (int i = 0; i < 4; i++) acc[mt][nt][i] = 0.f;

    // ---- prologue: chunk 0 into stage 0 ------------------------------------
#pragma unroll
    for (int it = 0; it < AIT; it++) CPASYNC16(aDst[it], aSrc[it]);
#pragma unroll
    for (int it = 0; it < 4; it++)   CPASYNC16(bDst[it], bSrc[it]);
    CPCOMMIT();

#pragma unroll 1
    for (int ch = 0; ch < 32; ch++) {
        const int s = ch & 1;
        if (ch < 31) {
            const uint32_t so = (uint32_t)(s ^ 1) * STAGE;
            const int ko = (ch + 1) * 32;
#pragma unroll
            for (int it = 0; it < AIT; it++) CPASYNC16(aDst[it] + so, aSrc[it] + ko);
#pragma unroll
            for (int it = 0; it < 4; it++)   CPASYNC16(bDst[it] + so, bSrc[it] + ko);
            CPCOMMIT();
            CPWAITG(1);
        } else {
            CPWAITG(0);
        }
        __syncthreads();

        const uint32_t As = sbase + (uint32_t)s * STAGE;
#pragma unroll
        for (int ks = 0; ks < 2; ks++) {
            const uint32_t khi = (ks * 32 + ksel) ^ xorv;
            const uint32_t klo = (64 + ks * 32 + ksel) ^ xorv;
            // B fragments first (16 regs live across the mt loop)
            uint32_t bh[4][2], bl[4][2];
#pragma unroll
            for (int ng = 0; ng < 2; ng++) {
                uint32_t r0, r1, r2, r3;
                LDSM4(r0, r1, r2, r3, As + bRow[ng] + khi);
                bh[2 * ng][0] = r0; bh[2 * ng][1] = r2;
                bh[2 * ng + 1][0] = r1; bh[2 * ng + 1][1] = r3;
                LDSM4(r0, r1, r2, r3, As + bRow[ng] + klo);
                bl[2 * ng][0] = r0; bl[2 * ng][1] = r2;
                bl[2 * ng + 1][0] = r1; bl[2 * ng + 1][1] = r3;
            }
            // A fragments just-in-time per m-subtile (8 regs)
#pragma unroll
            for (int mt = 0; mt < MT; mt++) {
                uint32_t ah[4], al[4];
                LDSM4(ah[0], ah[1], ah[2], ah[3], As + aRow[mt] + khi);
                LDSM4(al[0], al[1], al[2], al[3], As + aRow[mt] + klo);
#pragma unroll
                for (int nt = 0; nt < 4; nt++) {
                    MMA16816(acc[mt][nt], ah, bh[nt]);
                    MMA16816(acc[mt][nt], ah, bl[nt]);
                    MMA16816(acc[mt][nt], al, bh[nt]);
                }
            }
        }
        __syncthreads();
    }

    // ---- epilogue ----------------------------------------------------------
    if (mode == 1) {
        // Fused: rope(v+bias), dot with q0, reduce -> scores[b, h, t]
        const int b = m0 >> 10;
        const int tbase = m0 & 1023;
        float2 bb[4], qv[4];
        const float2* tabp[4];
#pragma unroll
        for (int nt = 0; nt < 4; nt++) {
            int col = n0 + wn + nt * 8 + 2 * tig;
            bb[nt] = *(const float2*)(bias + col);
            qv[nt] = *(const float2*)(q0 + b * 1024 + col);
            tabp[nt] = tab + ((col & 63) >> 1);
        }
        float* spart = (float*)dyn;      // [MTILE][4] partials
#pragma unroll
        for (int mt = 0; mt < MT; mt++) {
#pragma unroll
            for (int half = 0; half < 2; half++) {
                int rl = wm + mt * 16 + gid + half * 8;      // local row
                int t = tbase + rl;
                float p_acc = 0.f;
#pragma unroll
                for (int nt = 0; nt < 4; nt++) {
                    float2 cssn = tabp[nt][t * 32];
                    float v0 = acc[mt][nt][half * 2]     + bb[nt].x;
                    float v1 = acc[mt][nt][half * 2 + 1] + bb[nt].y;
                    float kw0 = v0 * cssn.x - v1 * cssn.y;
                    float kw1 = v1 * cssn.x + v0 * cssn.y;
                    p_acc = fmaf(qv[nt].x, kw0, p_acc);
                    p_acc = fmaf(qv[nt].y, kw1, p_acc);
                }
                p_acc += __shfl_xor_sync(0xffffffffu, p_acc, 1);
                p_acc += __shfl_xor_sync(0xffffffffu, p_acc, 2);
                if (tig == 0) spart[rl * 4 + (wn >> 5)] = p_acc;
            }
        }
        __syncthreads();
        if (tid < MTILE) {
            int t = tbase + tid;
            float s0 = (spart[tid * 4 + 0] + spart[tid * 4 + 1]) * 0.125f;
            float s1 = (spart[tid * 4 + 2] + spart[tid * 4 + 3]) * 0.125f;
            int h0 = n0 >> 6;
            scores[((b * 16 + h0)     << 10) + t] = s0;
            scores[((b * 16 + h0 + 1) << 10) + t] = s1;
        }
    } else {
#pragma unroll
        for (int mt = 0; mt < MT; mt++) {
#pragma unroll
            for (int half = 0; half < 2; half++) {
                int row = m0 + wm + mt * 16 + gid + half * 8;
#pragma unroll
                for (int nt = 0; nt < 4; nt++) {
                    int col = n0 + wn + nt * 8 + 2 * tig;
                    float v0 = acc[mt][nt][half * 2];
                    float v1 = acc[mt][nt][half * 2 + 1];
                    __nv_bfloat16 h0 = __float2bfloat16(v0);
                    __nv_bfloat16 h1 = __float2bfloat16(v1);
                    __nv_bfloat162 hp, lp;
                    hp.x = h0; hp.y = h1;
                    lp.x = __float2bfloat16(v0 - __bfloat162float(h0));
                    lp.y = __float2bfloat16(v1 - __bfloat162float(h1));
                    size_t o = (size_t)row * 1024 + col;
                    *(__nv_bfloat162*)(Chi + o) = hp;
                    *(__nv_bfloat162*)(Clo + o) = lp;
                }
            }
        }
    }
}

// ---------------------------------------------------------------------------
// Masked softmax over scores rows -> row0. grid 64 (b*16+h), 256 threads.
// ---------------------------------------------------------------------------
__global__ __launch_bounds__(256) void softmax_kernel(const int* __restrict__ mask,
                                                      const float* __restrict__ scores,
                                                      float* __restrict__ row0)
{
    int bh = blockIdx.x;
    int b = bh >> 4;
    __shared__ float sc[1024];
    __shared__ float red[8];
    __shared__ float bc;
    int tid = threadIdx.x;

    float lmax = -3.4e38f;
#pragma unroll
    for (int it = 0; it < 4; it++) {
        int t = it * 256 + tid;
        float s = scores[(bh << 10) + t];
        s = (mask[b * 1024 + t] == 0) ? -1e9f : s;
        sc[t] = s;
        lmax = fmaxf(lmax, s);
    }
#pragma unroll
    for (int o = 16; o; o >>= 1) lmax = fmaxf(lmax, __shfl_xor_sync(0xffffffffu, lmax, o));
    if ((tid & 31) == 0) red[tid >> 5] = lmax;
    __syncthreads();
    if (tid == 0) {
        float m = red[0];
        for (int i = 1; i < 8; i++) m = fmaxf(m, red[i]);
        bc = m;
    }
    __syncthreads();
    float gmax = bc;

    float lsum = 0.f;
#pragma unroll
    for (int it = 0; it < 4; it++) {
        int t = it * 256 + tid;
        float e = expf(sc[t] - gmax);
        sc[t] = e;
        lsum += e;
    }
#pragma unroll
    for (int o = 16; o; o >>= 1) lsum += __shfl_xor_sync(0xffffffffu, lsum, o);
    if ((tid & 31) == 0) red[tid >> 5] = lsum;
    __syncthreads();
    if (tid == 0) {
        float s = 0.f;
        for (int i = 0; i < 8; i++) s += red[i];
        bc = 1.f / s;
    }
    __syncthreads();
    float invs = bc;
#pragma unroll
    for (int it = 0; it < 4; it++) {
        int t = it * 256 + tid;
        row0[(bh << 10) + t] = sc[t] * invs;
    }
}

// ---------------------------------------------------------------------------
// Conv1d(16 -> 1024, k=3, pad=1) + bias + relu
// ---------------------------------------------------------------------------
#define OPB 16
__global__ __launch_bounds__(256) void conv_kernel(const float* __restrict__ cw,
                                                   const float* __restrict__ cb,
                                                   const float* __restrict__ row0,
                                                   float* __restrict__ out)
{
    int lc = blockIdx.x, og = blockIdx.y, b = blockIdx.z;
    __shared__ float tile[16][264];
    __shared__ float ws[OPB * 48];
    __shared__ float wb[OPB];
    int tid = threadIdx.x;

    for (int idx = tid; idx < OPB * 48; idx += 256) {
        int o = og * OPB + idx / 48;
        ws[idx] = cw[o * 48 + (idx % 48)];
    }
    if (tid < OPB) wb[tid] = cb[og * OPB + tid];
    for (int idx = tid; idx < 16 * 258; idx += 256) {
        int c = idx / 258, x = idx % 258;
        int l = lc * 256 - 1 + x;
        tile[c][x] = (l >= 0 && l < SS) ? row0[((long long)(b * 16 + c)) * SS + l] : 0.f;
    }
    __syncthreads();

    float acc[OPB];
#pragma unroll
    for (int o = 0; o < OPB; o++) acc[o] = wb[o];
#pragma unroll
    for (int c = 0; c < 16; c++) {
        float r0 = tile[c][tid], r1 = tile[c][tid + 1], r2 = tile[c][tid + 2];
#pragma unroll
        for (int o = 0; o < OPB; o++) {
            acc[o] = fmaf(r0, ws[o * 48 + c * 3],     acc[o]);
            acc[o] = fmaf(r1, ws[o * 48 + c * 3 + 1], acc[o]);
            acc[o] = fmaf(r2, ws[o * 48 + c * 3 + 2], acc[o]);
        }
    }
    int l = lc * 256 + tid;
#pragma unroll
    for (int o = 0; o < OPB; o++)
        out[((long long)(b * 1024 + og * OPB + o)) * SS + l] = fmaxf(acc[o], 0.f);
}

// ---------------------------------------------------------------------------
extern "C" void kernel_launch(void* const* d_in, const int* in_sizes, int n_in,
                              void* d_out, int out_size)
{
    const float* X    = (const float*)d_in[0];
    const int*   mask = (const int*)d_in[1];
    const float* W_G  = (const float*)d_in[2];
    const float* b_G  = (const float*)d_in[3];
    const float* Wq   = (const float*)d_in[4];
    const float* bq   = (const float*)d_in[5];
    const float* Wk   = (const float*)d_in[6];
    const float* bk   = (const float*)d_in[7];
    const float* cw   = (const float*)d_in[8];
    const float* cb   = (const float*)d_in[9];
    float* out = (float*)d_out;

    __nv_bfloat16 *pXhi, *pXlo, *pWGhi, *pWGlo, *pWkThi, *pWkTlo, *pCThi, *pCTlo;
    float *pbiask, *pg0, *pq0, *pscores, *prow0;
    float2* ptab;
    cudaGetSymbolAddress((void**)&pXhi,    g_Xhi);
    cudaGetSymbolAddress((void**)&pXlo,    g_Xlo);
    cudaGetSymbolAddress((void**)&pWGhi,   g_WGhi);
    cudaGetSymbolAddress((void**)&pWGlo,   g_WGlo);
    cudaGetSymbolAddress((void**)&pWkThi,  g_WkThi);
    cudaGetSymbolAddress((void**)&pWkTlo,  g_WkTlo);
    cudaGetSymbolAddress((void**)&pCThi,   g_WGKThi);
    cudaGetSymbolAddress((void**)&pCTlo,   g_WGKTlo);
    cudaGetSymbolAddress((void**)&pbiask,  g_biask);
    cudaGetSymbolAddress((void**)&pg0,     g_g0);
    cudaGetSymbolAddress((void**)&pq0,     g_q0);
    cudaGetSymbolAddress((void**)&pscores, g_scores);
    cudaGetSymbolAddress((void**)&prow0,   g_row0);
    cudaGetSymbolAddress((void**)&ptab,    g_tab);

    static int smem_set = 0;
    if (!smem_set) {
        cudaFuncSetAttribute(mmagemm<128>, cudaFuncAttributeMaxDynamicSharedMemorySize, 66560);
        cudaFuncSetAttribute(mmagemm<64>,  cudaFuncAttributeMaxDynamicSharedMemorySize, 50176);
        smem_set = 1;
    }

    // RoPE table + small GEMVs
    tab_kernel<<<128, 256>>>(ptab);
    gemv_fast<<<dim3(32, 1), 256>>>(b_G, Wk, bk, pbiask, 0LL);
    gemv_fast<<<dim3(32, 4), 256>>>(X, W_G, b_G, pg0, (long long)SS * DD);
    gemv_fast<<<dim3(32, 4), 256>>>(pg0, Wq, bq, pq0, 1024LL);

    // Conversions
    split_kernel<<<4096, 256>>>((const float4*)X, (__nv_bfloat162*)pXhi,
                                (__nv_bfloat162*)pXlo, BB * SS * DD / 4);
    split_kernel<<<1024, 256>>>((const float4*)W_G, (__nv_bfloat162*)pWGhi,
                                (__nv_bfloat162*)pWGlo, DD * DD / 4);
    transpose_split_kernel<<<dim3(32, 32), dim3(32, 8)>>>(Wk, pWkThi, pWkTlo);

    // GEMM1: WGK^T (A = Wk^T, B = W_G), split-write bf16
    mmagemm<64><<<dim3(8, 16), 256, 50176>>>(pWkThi, pWkTlo, pWGhi, pWGlo, 0,
                                             nullptr, nullptr, nullptr, nullptr,
                                             pCThi, pCTlo);
    // GEMM2 fused: scores = q0 . rope(X @ WGK + biask) / 8
    mmagemm<128><<<dim3(8, 32), 256, 66560>>>(pXhi, pXlo, pCThi, pCTlo, 1,
                                              pbiask, pq0, ptab, pscores,
                                              nullptr, nullptr);

    softmax_kernel<<<64, 256>>>(mask, pscores, prow0);
    conv_kernel<<<dim3(4, 64, 4), 256>>>(cw, cb, prow0, out);
}